// round 16
// baseline (speedup 1.0000x reference)
#include <cuda_runtime.h>
#include <cuda_fp16.h>
#include <cstdint>

#define NHEAD 32
#define DK    8
#define EDIM  256
#define MAXTOK (16 * 4096)

// fp16 copy of W (static __device__: no allocation, graph-capture safe).
__device__ __half g_Wh[EDIM * EDIM];

__device__ __forceinline__ unsigned packh2(float a, float b) {
    __half2 t = __floats2half2_rn(a, b);
    return *reinterpret_cast<unsigned*>(&t);
}
__device__ __forceinline__ float ex2f(float x) {
    float r; asm("ex2.approx.f32 %0, %1;" : "=f"(r) : "f"(x)); return r;
}

__device__ __forceinline__ void mma_k8(float* d, unsigned a0, unsigned a1, unsigned b0) {
    asm volatile(
        "mma.sync.aligned.m16n8k8.row.col.f32.f16.f16.f32 "
        "{%0,%1,%2,%3}, {%4,%5}, {%6}, {%0,%1,%2,%3};\n"
        : "+f"(d[0]), "+f"(d[1]), "+f"(d[2]), "+f"(d[3])
        : "r"(a0), "r"(a1), "r"(b0));
}
__device__ __forceinline__ void mma_k16(float* d, const unsigned* a, const unsigned* b) {
    asm volatile(
        "mma.sync.aligned.m16n8k16.row.col.f32.f16.f16.f32 "
        "{%0,%1,%2,%3}, {%4,%5,%6,%7}, {%8,%9}, {%0,%1,%2,%3};\n"
        : "+f"(d[0]), "+f"(d[1]), "+f"(d[2]), "+f"(d[3])
        : "r"(a[0]), "r"(a[1]), "r"(a[2]), "r"(a[3]), "r"(b[0]), "r"(b[1]));
}

// ---------------------------------------------------------------------------
// Kernel 0: W (fp32) -> g_Wh (fp16). 65536 elems, 8 per thread.
// ---------------------------------------------------------------------------
__global__ void __launch_bounds__(256) wconv_kernel(const float* __restrict__ W)
{
    const int i = (blockIdx.x * 256 + threadIdx.x) * 8;
    float v[8];
    *reinterpret_cast<float4*>(v)     = *reinterpret_cast<const float4*>(W + i);
    *reinterpret_cast<float4*>(v + 4) = *reinterpret_cast<const float4*>(W + i + 4);
    uint4 h;
    h.x = packh2(v[0], v[1]); h.y = packh2(v[2], v[3]);
    h.z = packh2(v[4], v[5]); h.w = packh2(v[6], v[7]);
    *reinterpret_cast<uint4*>(g_Wh + i) = h;
}

// ---------------------------------------------------------------------------
// Fused kernel: 64 tokens per CTA, 256 threads (8 warps).
// Phase 1 (attn): each warp runs the R14 tensor-core attention for 8 tokens,
//   writing fp16 results into the resident smem A tile As[64][AS_STR].
// Phase 2 (GEMM): C[64,256] = As @ Wh^T + bias; A-fragments read directly
//   from the resident tile, W streamed through Hs[256][40] in 8 K-chunks.
// ---------------------------------------------------------------------------
#define TKN    64
#define AS_STR 264      // halves; fragment LDS banks (4*gid+tig)%32 all distinct
#define HS_STR 40       // halves; proven conflict-free (R12)
#define QT_STR 36

#define AS_OFF 0
#define HS_OFF (TKN * AS_STR * 2)                 // 33792
#define QA_OFF (HS_OFF + 256 * HS_STR * 2)        // 54272
#define QT_OFF (QA_OFF + 8 * NHEAD * DK * 2)      // 58368
#define SMEM_TOT (QT_OFF + 8 * DK * QT_STR * 2)   // 62976

__global__ void __launch_bounds__(256) fused_kernel(
    const float* __restrict__ x,
    const float* __restrict__ theta,
    const float* __restrict__ bias,
    float* __restrict__ C, int ntok)
{
    extern __shared__ __align__(16) char smem[];
    __half* As = reinterpret_cast<__half*>(smem + AS_OFF);
    __half* Hs = reinterpret_cast<__half*>(smem + HS_OFF);

    const int tid  = threadIdx.x;
    const int warp = tid >> 5;
    const int lane = tid & 31;
    const int gid  = lane >> 2;
    const int tig  = lane & 3;
    const int m0   = blockIdx.x * TKN;

    __half* qA = reinterpret_cast<__half*>(smem + QA_OFF) + warp * (NHEAD * DK);
    __half* qT = reinterpret_cast<__half*>(smem + QT_OFF) + warp * (DK * QT_STR);

    const float4 th0 = *reinterpret_cast<const float4*>(theta);
    const float4 th1 = *reinterpret_cast<const float4*>(theta + 4);

    // =========================== Phase 1: attention ===========================
    for (int it = 0; it < 8; ++it) {
        const int tl  = warp * 8 + it;
        const int tok = m0 + tl;
        if (tok < ntok) {
            float q[8];
            {
                const float4* xp = reinterpret_cast<const float4*>(
                    x + (size_t)tok * EDIM + lane * DK);
                const float4 a = xp[0], b = xp[1];
                q[0] = __cosf(a.x + th0.x); q[1] = __cosf(a.y + th0.y);
                q[2] = __cosf(a.z + th0.z); q[3] = __cosf(a.w + th0.w);
                q[4] = __cosf(b.x + th1.x); q[5] = __cosf(b.y + th1.y);
                q[6] = __cosf(b.z + th1.z); q[7] = __cosf(b.w + th1.w);
            }
            {
                uint4 h;
                h.x = packh2(q[0], q[1]); h.y = packh2(q[2], q[3]);
                h.z = packh2(q[4], q[5]); h.w = packh2(q[6], q[7]);
                *reinterpret_cast<uint4*>(&qA[lane * DK]) = h;
            }
#pragma unroll
            for (int d = 0; d < 8; ++d)
                qT[d * QT_STR + lane] = __float2half_rn(q[d]);
            __syncwarp();

            unsigned agr[2][2], bgr[4];
#pragma unroll
            for (int mt = 0; mt < 2; ++mt) {
                agr[mt][0] = *reinterpret_cast<const unsigned*>(&qA[(mt * 16 + gid) * DK + 2 * tig]);
                agr[mt][1] = *reinterpret_cast<const unsigned*>(&qA[(mt * 16 + gid + 8) * DK + 2 * tig]);
            }
#pragma unroll
            for (int nt = 0; nt < 4; ++nt)
                bgr[nt] = *reinterpret_cast<const unsigned*>(&qA[(nt * 8 + gid) * DK + 2 * tig]);

            float sc[2][4][4];
#pragma unroll
            for (int mt = 0; mt < 2; ++mt)
#pragma unroll
                for (int nt = 0; nt < 4; ++nt) {
#pragma unroll
                    for (int c = 0; c < 4; ++c) sc[mt][nt][c] = 0.f;
                    mma_k8(sc[mt][nt], agr[mt][0], agr[mt][1], bgr[nt]);
                }

            const float CSC = 0.5100420914154853f;
            float w[2][4][4];
            float rs[2][2] = {{0.f, 0.f}, {0.f, 0.f}};
#pragma unroll
            for (int mt = 0; mt < 2; ++mt)
#pragma unroll
                for (int nt = 0; nt < 4; ++nt) {
                    w[mt][nt][0] = ex2f(sc[mt][nt][0] * CSC);
                    w[mt][nt][1] = ex2f(sc[mt][nt][1] * CSC);
                    w[mt][nt][2] = ex2f(sc[mt][nt][2] * CSC);
                    w[mt][nt][3] = ex2f(sc[mt][nt][3] * CSC);
                    rs[mt][0] += w[mt][nt][0] + w[mt][nt][1];
                    rs[mt][1] += w[mt][nt][2] + w[mt][nt][3];
                }
#pragma unroll
            for (int mt = 0; mt < 2; ++mt)
#pragma unroll
                for (int r = 0; r < 2; ++r) {
                    rs[mt][r] += __shfl_xor_sync(0xFFFFFFFFu, rs[mt][r], 1);
                    rs[mt][r] += __shfl_xor_sync(0xFFFFFFFFu, rs[mt][r], 2);
                }

            unsigned wh[2][4][2];
#pragma unroll
            for (int mt = 0; mt < 2; ++mt)
#pragma unroll
                for (int nt = 0; nt < 4; ++nt) {
                    wh[mt][nt][0] = packh2(w[mt][nt][0], w[mt][nt][1]);
                    wh[mt][nt][1] = packh2(w[mt][nt][2], w[mt][nt][3]);
                }

            unsigned bq[2][2];
#pragma unroll
            for (int kc = 0; kc < 2; ++kc) {
                bq[kc][0] = *reinterpret_cast<const unsigned*>(&qT[gid * QT_STR + kc * 16 + 2 * tig]);
                bq[kc][1] = *reinterpret_cast<const unsigned*>(&qT[gid * QT_STR + kc * 16 + 2 * tig + 8]);
            }

            float o[2][4];
#pragma unroll
            for (int mt = 0; mt < 2; ++mt) {
#pragma unroll
                for (int c = 0; c < 4; ++c) o[mt][c] = 0.f;
#pragma unroll
                for (int kc = 0; kc < 2; ++kc) {
                    unsigned af[4] = { wh[mt][2 * kc][0], wh[mt][2 * kc][1],
                                       wh[mt][2 * kc + 1][0], wh[mt][2 * kc + 1][1] };
                    mma_k16(o[mt], af, bq[kc]);
                }
            }

            // store fp16 row into the resident A tile (conflict-free)
            __half* arow = As + (size_t)tl * AS_STR;
#pragma unroll
            for (int mt = 0; mt < 2; ++mt) {
                const float inv0 = 1.0f / rs[mt][0];
                const float inv1 = 1.0f / rs[mt][1];
                *reinterpret_cast<unsigned*>(&arow[(mt * 16 + gid) * DK + 2 * tig]) =
                    packh2(o[mt][0] * inv0, o[mt][1] * inv0);
                *reinterpret_cast<unsigned*>(&arow[(mt * 16 + gid + 8) * DK + 2 * tig]) =
                    packh2(o[mt][2] * inv1, o[mt][3] * inv1);
            }
        }
        __syncwarp();
    }
    __syncthreads();

    // ============================ Phase 2: GEMM ==============================
    // warp tile: M 32 (wm) x N 64 (wn); fi in {0,1}, fj in 0..7
    const int wm = warp >> 2;        // 0..1
    const int wn = warp & 3;         // 0..3

    float acc[2][8][4];
#pragma unroll
    for (int i = 0; i < 2; ++i)
#pragma unroll
        for (int j = 0; j < 8; ++j)
#pragma unroll
            for (int c = 0; c < 4; ++c) acc[i][j][c] = 0.f;

    for (int kc = 0; kc < 8; ++kc) {
        __syncthreads();             // protect Hs from previous iteration readers
        // load Hs tile: 256 rows x 32 halves = 1024 uint4; 4 per thread
#pragma unroll
        for (int j = 0; j < 4; ++j) {
            const int idx = j * 256 + tid;
            const int row = idx >> 2;
            const int c8  = (idx & 3) * 8;
            const uint4 v = *reinterpret_cast<const uint4*>(
                g_Wh + (size_t)row * EDIM + kc * 32 + c8);
            *reinterpret_cast<uint4*>(&Hs[row * HS_STR + c8]) = v;
        }
        __syncthreads();

#pragma unroll
        for (int ks = 0; ks < 2; ++ks) {
            const int kk = ks * 16 + tig * 2;          // within Hs chunk
            const int ck = kc * 32 + kk;               // within As full row
            unsigned af[2][4], hf[8][2];
#pragma unroll
            for (int fi = 0; fi < 2; ++fi) {
                const int r = wm * 32 + fi * 16 + gid;
                af[fi][0] = *reinterpret_cast<const unsigned*>(&As[r * AS_STR + ck]);
                af[fi][1] = *reinterpret_cast<const unsigned*>(&As[(r + 8) * AS_STR + ck]);
                af[fi][2] = *reinterpret_cast<const unsigned*>(&As[r * AS_STR + ck + 8]);
                af[fi][3] = *reinterpret_cast<const unsigned*>(&As[(r + 8) * AS_STR + ck + 8]);
            }
#pragma unroll
            for (int fj = 0; fj < 8; ++fj) {
                const int r = wn * 64 + fj * 8 + gid;
                hf[fj][0] = *reinterpret_cast<const unsigned*>(&Hs[r * HS_STR + kk]);
                hf[fj][1] = *reinterpret_cast<const unsigned*>(&Hs[r * HS_STR + kk + 8]);
            }
#pragma unroll
            for (int fi = 0; fi < 2; ++fi)
#pragma unroll
                for (int fj = 0; fj < 8; ++fj)
                    mma_k16(acc[fi][fj], af[fi], hf[fj]);
        }
    }

    // Epilogue: bias + fp32 store
#pragma unroll
    for (int fj = 0; fj < 8; ++fj) {
        const int col = wn * 64 + fj * 8 + tig * 2;
        const float2 bv = *reinterpret_cast<const float2*>(&bias[col]);
#pragma unroll
        for (int fi = 0; fi < 2; ++fi) {
            const int r0 = m0 + wm * 32 + fi * 16 + gid;
            if (r0 < ntok)
                *reinterpret_cast<float2*>(&C[(size_t)r0 * EDIM + col]) =
                    make_float2(acc[fi][fj][0] + bv.x, acc[fi][fj][1] + bv.y);
            const int r1 = r0 + 8;
            if (r1 < ntok)
                *reinterpret_cast<float2*>(&C[(size_t)r1 * EDIM + col]) =
                    make_float2(acc[fi][fj][2] + bv.x, acc[fi][fj][3] + bv.y);
        }
    }
}

// ---------------------------------------------------------------------------
extern "C" void kernel_launch(void* const* d_in, const int* in_sizes, int n_in,
                              void* d_out, int out_size)
{
    const float* x     = (const float*)d_in[0];
    const float* theta = (const float*)d_in[1];
    const float* W     = (const float*)d_in[2];
    const float* bias  = (const float*)d_in[3];
    float* out = (float*)d_out;

    int ntok = in_sizes[0] / EDIM;
    if (ntok > MAXTOK) ntok = MAXTOK;

    static bool attr_done = false;
    if (!attr_done) {
        cudaFuncSetAttribute(fused_kernel,
                             cudaFuncAttributeMaxDynamicSharedMemorySize, SMEM_TOT);
        attr_done = true;
    }

    wconv_kernel<<<EDIM * EDIM / (256 * 8), 256>>>(W);
    fused_kernel<<<(ntok + TKN - 1) / TKN, 256, SMEM_TOT>>>(x, theta, bias, out, ntok);
}

// round 17
// speedup vs baseline: 1.1754x; 1.1754x over previous
#include <cuda_runtime.h>
#include <cuda_fp16.h>
#include <cstdint>

#define NHEAD 32
#define DK    8
#define EDIM  256
#define MAXTOK (16 * 4096)

// Scratch (static __device__: no allocation, graph-capture safe).
__device__ __half g_mid[(size_t)MAXTOK * EDIM];
__device__ __half g_Wh[EDIM * EDIM];

__device__ __forceinline__ unsigned packh2(float a, float b) {
    __half2 t = __floats2half2_rn(a, b);
    return *reinterpret_cast<unsigned*>(&t);
}
__device__ __forceinline__ float ex2f(float x) {
    float r; asm("ex2.approx.f32 %0, %1;" : "=f"(r) : "f"(x)); return r;
}
__device__ __forceinline__ uint32_t smem_u32(const void* p) {
    uint32_t a;
    asm("{ .reg .u64 t; cvta.to.shared.u64 t, %1; cvt.u32.u64 %0, t; }" : "=r"(a) : "l"(p));
    return a;
}
// 16B async copy; pred=false -> zero-fill (src-size 0)
__device__ __forceinline__ void cpa16(uint32_t dst, const void* src, bool v) {
    asm volatile("cp.async.ca.shared.global [%0], [%1], 16, %2;"
                 :: "r"(dst), "l"(src), "r"(v ? 16u : 0u) : "memory");
}

__device__ __forceinline__ void mma_k8(float* d, unsigned a0, unsigned a1, unsigned b0) {
    asm volatile(
        "mma.sync.aligned.m16n8k8.row.col.f32.f16.f16.f32 "
        "{%0,%1,%2,%3}, {%4,%5}, {%6}, {%0,%1,%2,%3};\n"
        : "+f"(d[0]), "+f"(d[1]), "+f"(d[2]), "+f"(d[3])
        : "r"(a0), "r"(a1), "r"(b0));
}
__device__ __forceinline__ void mma_k16(float* d, const unsigned* a, const unsigned* b) {
    asm volatile(
        "mma.sync.aligned.m16n8k16.row.col.f32.f16.f16.f32 "
        "{%0,%1,%2,%3}, {%4,%5,%6,%7}, {%8,%9}, {%0,%1,%2,%3};\n"
        : "+f"(d[0]), "+f"(d[1]), "+f"(d[2]), "+f"(d[3])
        : "r"(a[0]), "r"(a[1]), "r"(a[2]), "r"(a[3]), "r"(b[0]), "r"(b[1]));
}

// ---------------------------------------------------------------------------
// Kernel 0: W (fp32) -> g_Wh (fp16). 65536 elems, 8 per thread.
// ---------------------------------------------------------------------------
__global__ void __launch_bounds__(256) wconv_kernel(const float* __restrict__ W)
{
    const int i = (blockIdx.x * 256 + threadIdx.x) * 8;
    float v[8];
    *reinterpret_cast<float4*>(v)     = *reinterpret_cast<const float4*>(W + i);
    *reinterpret_cast<float4*>(v + 4) = *reinterpret_cast<const float4*>(W + i + 4);
    uint4 h;
    h.x = packh2(v[0], v[1]); h.y = packh2(v[2], v[3]);
    h.z = packh2(v[4], v[5]); h.w = packh2(v[6], v[7]);
    *reinterpret_cast<uint4*>(g_Wh + i) = h;
}

// ---------------------------------------------------------------------------
// Kernel 1: tensor-core quantum attention (identical to round 14).
// ---------------------------------------------------------------------------
#define QT_STR 36

__global__ void __launch_bounds__(128) attn_kernel(
    const float* __restrict__ x,
    const float* __restrict__ theta,
    int ntok)
{
    __shared__ __align__(16) __half qA[4][NHEAD][DK];
    __shared__ __align__(16) __half qT[4][DK][QT_STR];
    const int wl   = threadIdx.x >> 5;
    const int lane = threadIdx.x & 31;
    const int gid  = lane >> 2;
    const int tig  = lane & 3;
    const int tok  = blockIdx.x * 4 + wl;
    if (tok >= ntok) return;

    const float4 th0 = *reinterpret_cast<const float4*>(theta);
    const float4 th1 = *reinterpret_cast<const float4*>(theta + 4);

    float q[8];
    {
        const float4* xp = reinterpret_cast<const float4*>(
            x + (size_t)tok * EDIM + lane * DK);
        const float4 a = xp[0], b = xp[1];
        q[0] = __cosf(a.x + th0.x); q[1] = __cosf(a.y + th0.y);
        q[2] = __cosf(a.z + th0.z); q[3] = __cosf(a.w + th0.w);
        q[4] = __cosf(b.x + th1.x); q[5] = __cosf(b.y + th1.y);
        q[6] = __cosf(b.z + th1.z); q[7] = __cosf(b.w + th1.w);
    }
    {
        uint4 h;
        h.x = packh2(q[0], q[1]); h.y = packh2(q[2], q[3]);
        h.z = packh2(q[4], q[5]); h.w = packh2(q[6], q[7]);
        *reinterpret_cast<uint4*>(&qA[wl][lane][0]) = h;
    }
#pragma unroll
    for (int d = 0; d < 8; ++d)
        qT[wl][d][lane] = __float2half_rn(q[d]);
    __syncwarp();

    unsigned agr[2][2], bgr[4];
#pragma unroll
    for (int mt = 0; mt < 2; ++mt) {
        agr[mt][0] = *reinterpret_cast<const unsigned*>(&qA[wl][mt * 16 + gid][2 * tig]);
        agr[mt][1] = *reinterpret_cast<const unsigned*>(&qA[wl][mt * 16 + gid + 8][2 * tig]);
    }
#pragma unroll
    for (int nt = 0; nt < 4; ++nt)
        bgr[nt] = *reinterpret_cast<const unsigned*>(&qA[wl][nt * 8 + gid][2 * tig]);

    float sc[2][4][4];
#pragma unroll
    for (int mt = 0; mt < 2; ++mt)
#pragma unroll
        for (int nt = 0; nt < 4; ++nt) {
#pragma unroll
            for (int c = 0; c < 4; ++c) sc[mt][nt][c] = 0.f;
            mma_k8(sc[mt][nt], agr[mt][0], agr[mt][1], bgr[nt]);
        }

    const float CSC = 0.5100420914154853f;
    float w[2][4][4];
    float rs[2][2] = {{0.f, 0.f}, {0.f, 0.f}};
#pragma unroll
    for (int mt = 0; mt < 2; ++mt)
#pragma unroll
        for (int nt = 0; nt < 4; ++nt) {
            w[mt][nt][0] = ex2f(sc[mt][nt][0] * CSC);
            w[mt][nt][1] = ex2f(sc[mt][nt][1] * CSC);
            w[mt][nt][2] = ex2f(sc[mt][nt][2] * CSC);
            w[mt][nt][3] = ex2f(sc[mt][nt][3] * CSC);
            rs[mt][0] += w[mt][nt][0] + w[mt][nt][1];
            rs[mt][1] += w[mt][nt][2] + w[mt][nt][3];
        }
#pragma unroll
    for (int mt = 0; mt < 2; ++mt)
#pragma unroll
        for (int r = 0; r < 2; ++r) {
            rs[mt][r] += __shfl_xor_sync(0xFFFFFFFFu, rs[mt][r], 1);
            rs[mt][r] += __shfl_xor_sync(0xFFFFFFFFu, rs[mt][r], 2);
        }

    unsigned wh[2][4][2];
#pragma unroll
    for (int mt = 0; mt < 2; ++mt)
#pragma unroll
        for (int nt = 0; nt < 4; ++nt) {
            wh[mt][nt][0] = packh2(w[mt][nt][0], w[mt][nt][1]);
            wh[mt][nt][1] = packh2(w[mt][nt][2], w[mt][nt][3]);
        }

    unsigned bq[2][2];
#pragma unroll
    for (int kc = 0; kc < 2; ++kc) {
        bq[kc][0] = *reinterpret_cast<const unsigned*>(&qT[wl][gid][kc * 16 + 2 * tig]);
        bq[kc][1] = *reinterpret_cast<const unsigned*>(&qT[wl][gid][kc * 16 + 2 * tig + 8]);
    }

    float o[2][4];
#pragma unroll
    for (int mt = 0; mt < 2; ++mt) {
#pragma unroll
        for (int c = 0; c < 4; ++c) o[mt][c] = 0.f;
#pragma unroll
        for (int kc = 0; kc < 2; ++kc) {
            unsigned af[4] = { wh[mt][2 * kc][0], wh[mt][2 * kc][1],
                               wh[mt][2 * kc + 1][0], wh[mt][2 * kc + 1][1] };
            mma_k16(o[mt], af, bq[kc]);
        }
    }

    __half* outp = g_mid + (size_t)tok * EDIM;
#pragma unroll
    for (int mt = 0; mt < 2; ++mt) {
        const float inv0 = 1.0f / rs[mt][0];
        const float inv1 = 1.0f / rs[mt][1];
        *reinterpret_cast<unsigned*>(&outp[(mt * 16 + gid) * DK + 2 * tig]) =
            packh2(o[mt][0] * inv0, o[mt][1] * inv0);
        *reinterpret_cast<unsigned*>(&outp[(mt * 16 + gid + 8) * DK + 2 * tig]) =
            packh2(o[mt][2] * inv1, o[mt][3] * inv1);
    }
}

// ---------------------------------------------------------------------------
// Kernel 2: C = A @ Wh^T + bias — fp16 mma, cp.async 2-stage pipeline.
// Block 128x128, GBK=32, 8 k-chunks. Loads go straight to smem (no register
// staging); wait_group 1 keeps one chunk in flight behind the compute.
// ---------------------------------------------------------------------------
#define GBM 128
#define GBN 128
#define GBK 32
#define KSTR 40
#define NKC  (EDIM / GBK)          // 8

__global__ void __launch_bounds__(256) gemm_pipe_kernel(
    const float* __restrict__ bias,
    float* __restrict__ C, int M)
{
    __shared__ __align__(16) __half As[2][GBM][KSTR];
    __shared__ __align__(16) __half Hs[2][GBN][KSTR];

    const int t    = threadIdx.x;
    const int warp = t >> 5;
    const int lane = t & 31;
    const int wm   = warp >> 2;      // 0..1  (M)
    const int wn   = warp & 3;       // 0..3  (N)
    const int gid  = lane >> 2;      // 0..7
    const int tig  = lane & 3;       // 0..3
    const int m0   = blockIdx.x * GBM;
    const int n0   = blockIdx.y * GBN;

    const int lr = t >> 2;           // 0..63 (rows; +64 second pass)
    const int lc = (t & 3) * 8;      // k offset (8 halves = 16B chunks)

    const __half* aB = g_mid + (size_t)m0 * EDIM;
    const __half* hB = g_Wh + (size_t)n0 * EDIM;
    const bool av0 = (m0 + lr) < M;
    const bool av1 = (m0 + lr + 64) < M;

    // per-thread smem dst addresses (stage 0; stage 1 = +stage offset)
    const uint32_t asBase = smem_u32(&As[0][0][0]);
    const uint32_t hsBase = smem_u32(&Hs[0][0][0]);
    const uint32_t stgA = GBM * KSTR * 2;     // bytes per A stage
    const uint32_t stgH = GBN * KSTR * 2;
    const uint32_t aD0 = asBase + (lr * KSTR + lc) * 2;
    const uint32_t aD1 = asBase + ((lr + 64) * KSTR + lc) * 2;
    const uint32_t hD0 = hsBase + (lr * KSTR + lc) * 2;
    const uint32_t hD1 = hsBase + ((lr + 64) * KSTR + lc) * 2;

    float acc[2][4][4];   // [fi 0..1? no: 4][4]... keep R12 shape
    float accf[4][4][4];
#pragma unroll
    for (int i = 0; i < 4; ++i)
#pragma unroll
        for (int j = 0; j < 4; ++j)
#pragma unroll
            for (int c = 0; c < 4; ++c) accf[i][j][c] = 0.f;
    (void)acc;

    // prologue: stage 0
    {
        const int kc = 0;
        cpa16(aD0, aB + (size_t)lr * EDIM + kc + lc, av0);
        cpa16(aD1, aB + (size_t)(lr + 64) * EDIM + kc + lc, av1);
        cpa16(hD0, hB + (size_t)lr * EDIM + kc + lc, true);
        cpa16(hD1, hB + (size_t)(lr + 64) * EDIM + kc + lc, true);
        asm volatile("cp.async.commit_group;" ::: "memory");
    }

    for (int it = 0; it < NKC; ++it) {
        const int buf = it & 1;
        if (it + 1 < NKC) {
            const int nb = (it + 1) & 1;
            const int kc = (it + 1) * GBK;
            cpa16(aD0 + nb * stgA, aB + (size_t)lr * EDIM + kc + lc, av0);
            cpa16(aD1 + nb * stgA, aB + (size_t)(lr + 64) * EDIM + kc + lc, av1);
            cpa16(hD0 + nb * stgH, hB + (size_t)lr * EDIM + kc + lc, true);
            cpa16(hD1 + nb * stgH, hB + (size_t)(lr + 64) * EDIM + kc + lc, true);
            asm volatile("cp.async.commit_group;" ::: "memory");
            asm volatile("cp.async.wait_group 1;" ::: "memory");
        } else {
            asm volatile("cp.async.wait_group 0;" ::: "memory");
        }
        __syncthreads();

#pragma unroll
        for (int ks = 0; ks < 2; ++ks) {
            const int kk = ks * 16 + tig * 2;
            unsigned af[4][4], hf[4][2];
#pragma unroll
            for (int fi = 0; fi < 4; ++fi) {
                const int r = wm * 64 + fi * 16 + gid;
                af[fi][0] = *reinterpret_cast<const unsigned*>(&As[buf][r][kk]);
                af[fi][1] = *reinterpret_cast<const unsigned*>(&As[buf][r + 8][kk]);
                af[fi][2] = *reinterpret_cast<const unsigned*>(&As[buf][r][kk + 8]);
                af[fi][3] = *reinterpret_cast<const unsigned*>(&As[buf][r + 8][kk + 8]);
            }
#pragma unroll
            for (int fj = 0; fj < 4; ++fj) {
                const int r = wn * 32 + fj * 8 + gid;
                hf[fj][0] = *reinterpret_cast<const unsigned*>(&Hs[buf][r][kk]);
                hf[fj][1] = *reinterpret_cast<const unsigned*>(&Hs[buf][r][kk + 8]);
            }
#pragma unroll
            for (int fi = 0; fi < 4; ++fi)
#pragma unroll
                for (int fj = 0; fj < 4; ++fj)
                    mma_k16(accf[fi][fj], af[fi], hf[fj]);
        }
        __syncthreads();    // all reads of buf done before it is refilled
    }

    // Epilogue: bias + fp32 store (float2 per fragment row).
#pragma unroll
    for (int fj = 0; fj < 4; ++fj) {
        const int col = n0 + wn * 32 + fj * 8 + tig * 2;
        const float2 bv = *reinterpret_cast<const float2*>(&bias[col]);
#pragma unroll
        for (int fi = 0; fi < 4; ++fi) {
            const int r0 = m0 + wm * 64 + fi * 16 + gid;
            if (r0 < M)
                *reinterpret_cast<float2*>(&C[(size_t)r0 * EDIM + col]) =
                    make_float2(accf[fi][fj][0] + bv.x, accf[fi][fj][1] + bv.y);
            const int r1 = r0 + 8;
            if (r1 < M)
                *reinterpret_cast<float2*>(&C[(size_t)r1 * EDIM + col]) =
                    make_float2(accf[fi][fj][2] + bv.x, accf[fi][fj][3] + bv.y);
        }
    }
}

// ---------------------------------------------------------------------------
extern "C" void kernel_launch(void* const* d_in, const int* in_sizes, int n_in,
                              void* d_out, int out_size)
{
    const float* x     = (const float*)d_in[0];
    const float* theta = (const float*)d_in[1];
    const float* W     = (const float*)d_in[2];
    const float* bias  = (const float*)d_in[3];
    float* out = (float*)d_out;

    int ntok = in_sizes[0] / EDIM;
    if (ntok > MAXTOK) ntok = MAXTOK;

    attn_kernel<<<(ntok + 3) / 4, 128>>>(x, theta, ntok);
    wconv_kernel<<<EDIM * EDIM / (256 * 8), 256>>>(W);

    dim3 grid((ntok + GBM - 1) / GBM, EDIM / GBN);
    gemm_pipe_kernel<<<grid, 256>>>(bias, out, ntok);
}